// round 8
// baseline (speedup 1.0000x reference)
#include <cuda_runtime.h>
#include <cuda_bf16.h>
#include <cstdint>

// ---------------------------------------------------------------------------
// Vanilla RNN: h_t = tanh(h_{t-1} @ wh + x_t @ wx + b), out = h_T  [B,1,H]
// B=256, T=2048, H=256 fp32.
// Phase 0: prep_w / prep_x — bf16 hi/lo splits of wx^T and x
// Phase 1: proj — xw = x @ wx + b via mma.sync bf16x3, cp.async pipelined
// Phase 2: scan — sequential recurrence, dense-plane smem layout
// (Resubmission of R7 after infra-failure round; code audited, unchanged.)
// ---------------------------------------------------------------------------

#define B_DIM 256
#define T_DIM 2048
#define H_DIM 256
#define M_TOTAL (B_DIM * T_DIM)

typedef unsigned long long u64;

__device__ float g_xw[(size_t)M_TOTAL * H_DIM];              // 512 MB scratch
__device__ __nv_bfloat16 g_wT_hi[H_DIM * H_DIM];             // wx^T hi, [n][k]
__device__ __nv_bfloat16 g_wT_lo[H_DIM * H_DIM];             // wx^T lo, [n][k]
__device__ __nv_bfloat16 g_xhi[(size_t)M_TOTAL * H_DIM];     // x hi (256 MB)
__device__ __nv_bfloat16 g_xlo[(size_t)M_TOTAL * H_DIM];     // x lo (256 MB)

// ------------------------- packed f32x2 helpers -----------------------------
__device__ __forceinline__ u64 f2fma(u64 a, u64 b, u64 c) {
    u64 d; asm("fma.rn.f32x2 %0,%1,%2,%3;" : "=l"(d) : "l"(a), "l"(b), "l"(c));
    return d;
}
__device__ __forceinline__ u64 f2add(u64 a, u64 b) {
    u64 d; asm("add.rn.f32x2 %0,%1,%2;" : "=l"(d) : "l"(a), "l"(b));
    return d;
}
__device__ __forceinline__ u64 dupf(float x) {
    u64 d; asm("mov.b64 %0,{%1,%1};" : "=l"(d) : "f"(x));
    return d;
}
__device__ __forceinline__ float2 upk(u64 d) {
    float2 v; asm("mov.b64 {%0,%1},%2;" : "=f"(v.x), "=f"(v.y) : "l"(d));
    return v;
}

// ------------------------- mma.sync / cp.async helpers ----------------------
__device__ __forceinline__ uint32_t smem_u32(const void* p) {
    uint32_t a;
    asm("{ .reg .u64 t; cvta.to.shared.u64 t, %1; cvt.u32.u64 %0, t; }"
        : "=r"(a) : "l"(p));
    return a;
}
__device__ __forceinline__ void ldsm_x4(uint32_t* r, uint32_t addr) {
    asm volatile("ldmatrix.sync.aligned.m8n8.x4.shared.b16 {%0,%1,%2,%3}, [%4];"
                 : "=r"(r[0]), "=r"(r[1]), "=r"(r[2]), "=r"(r[3]) : "r"(addr));
}
__device__ __forceinline__ void mma_bf16(float* d, const uint32_t* a,
                                         const uint32_t* b) {
    asm volatile(
        "mma.sync.aligned.m16n8k16.row.col.f32.bf16.bf16.f32 "
        "{%0,%1,%2,%3},{%4,%5,%6,%7},{%8,%9},{%0,%1,%2,%3};"
        : "+f"(d[0]), "+f"(d[1]), "+f"(d[2]), "+f"(d[3])
        : "r"(a[0]), "r"(a[1]), "r"(a[2]), "r"(a[3]), "r"(b[0]), "r"(b[1]));
}
__device__ __forceinline__ void cp16(uint32_t dst, const void* src) {
    asm volatile("cp.async.cg.shared.global [%0], [%1], 16;"
                 :: "r"(dst), "l"(src));
}
#define CP_COMMIT() asm volatile("cp.async.commit_group;" ::: "memory")
#define CP_WAIT(n)  asm volatile("cp.async.wait_group %0;" :: "n"(n) : "memory")

// ---------------------------------------------------------------------------
// Prep kernels
// ---------------------------------------------------------------------------
__global__ void prep_w(const float* __restrict__ wx) {
    int k = blockIdx.x;
    int n = threadIdx.x;
    float v = wx[k * H_DIM + n];
    __nv_bfloat16 hi = __float2bfloat16(v);
    __nv_bfloat16 lo = __float2bfloat16(v - __bfloat162float(hi));
    g_wT_hi[n * H_DIM + k] = hi;
    g_wT_lo[n * H_DIM + k] = lo;
}

// one float4 per thread; writes packed u64 (4 bf16) to hi and lo planes
__global__ __launch_bounds__(256) void prep_x(const float4* __restrict__ x) {
    size_t i = (size_t)blockIdx.x * 256 + threadIdx.x;
    float4 v = x[i];
    __nv_bfloat16 h0 = __float2bfloat16(v.x);
    __nv_bfloat16 h1 = __float2bfloat16(v.y);
    __nv_bfloat16 h2 = __float2bfloat16(v.z);
    __nv_bfloat16 h3 = __float2bfloat16(v.w);
    __nv_bfloat16 l0 = __float2bfloat16(v.x - __bfloat162float(h0));
    __nv_bfloat16 l1 = __float2bfloat16(v.y - __bfloat162float(h1));
    __nv_bfloat16 l2 = __float2bfloat16(v.z - __bfloat162float(h2));
    __nv_bfloat16 l3 = __float2bfloat16(v.w - __bfloat162float(h3));
    __nv_bfloat162 hp0{h0, h1}, hp1{h2, h3}, lp0{l0, l1}, lp1{l2, l3};
    u64 hw = (u64)(*(uint32_t*)&hp0) | ((u64)(*(uint32_t*)&hp1) << 32);
    u64 lw = (u64)(*(uint32_t*)&lp0) | ((u64)(*(uint32_t*)&lp1) << 32);
    ((u64*)g_xhi)[i] = hw;
    ((u64*)g_xlo)[i] = lw;
}

// ---------------------------------------------------------------------------
// Proj: xw[m,n] = sum_k x[m,k] wx[k,n] + b[n] via mma.sync bf16x3.
// CTA: 128x128 tile, 256 threads (8 warps, each 32x64).
// W (hi+lo, full K=256) resident in smem, staged ONCE via cp.async.
// A chunks (PBK=64) double-buffered via cp.async.
// ---------------------------------------------------------------------------
#define PM 128
#define PN 128
#define PBK 64
#define LDA_B 144                       // A row stride (64 bf16 + pad)
#define LDW_B 528                       // W row stride (256 bf16 + pad)

#define SW_HI 0
#define SW_LO (SW_HI + PN * LDW_B)      // 67584
#define SA0   (SW_LO + PN * LDW_B)      // 135168
#define A_BUF (PM * LDA_B)              // 18432
#define SBIAS (SA0 + 4 * A_BUF)         // 208896
#define PS_TOTAL (SBIAS + PN * 4)       // 209408

__global__ __launch_bounds__(256) void proj_kernel(const float* __restrict__ bias)
{
    extern __shared__ __align__(128) char sm[];
    const uint32_t smb = smem_u32(sm);
    const int tid  = threadIdx.x;
    const int wid  = tid >> 5;
    const int lane = tid & 31;
    const int n0 = blockIdx.x * PN;
    const long m0 = (long)blockIdx.y * PM;
    const int wm = (wid >> 1) * 32;
    const int wn = (wid & 1) * 64;

    // ---- stage W (hi+lo, all K) once: 8192 x 16B chunks ----
#pragma unroll
    for (int i = 0; i < 32; ++i) {
        int e = tid + i * 256;
        int term = e >> 12;             // 0: hi, 1: lo
        int r = e & 4095;
        int n = r >> 5;                 // 0..127
        int c = r & 31;                 // 16B chunk within k (8 bf16)
        uint32_t dst = smb + (term ? SW_LO : SW_HI) + n * LDW_B + c * 16;
        const __nv_bfloat16* src =
            (term ? g_wT_lo : g_wT_hi) + (n0 + n) * H_DIM + c * 8;
        cp16(dst, src);
    }
    CP_COMMIT();

    // ---- stage A chunk 0 ----
    {
        const long k0 = 0;
#pragma unroll
        for (int i = 0; i < 8; ++i) {
            int e = tid + i * 256;
            int term = e >> 10;
            int r = e & 1023;
            int row = r >> 3;
            int c = r & 7;
            uint32_t dst = smb + SA0 + (term ? A_BUF : 0) + row * LDA_B + c * 16;
            const __nv_bfloat16* src =
                (term ? g_xlo : g_xhi) + (m0 + row) * H_DIM + k0 + c * 8;
            cp16(dst, src);
        }
    }
    CP_COMMIT();

    if (tid < PN) ((float*)(sm + SBIAS))[tid] = bias[n0 + tid];

    float d[2][8][4];
#pragma unroll
    for (int mt = 0; mt < 2; ++mt)
#pragma unroll
        for (int nt = 0; nt < 8; ++nt)
#pragma unroll
            for (int i = 0; i < 4; ++i) d[mt][nt][i] = 0.0f;

    const int a_row = lane & 15;
    const int a_c8  = (lane >> 4) * 8;
    const int b_sel = lane >> 3;
    const int b_nof = (b_sel >> 1) * 8 + (lane & 7);
    const int b_kof = (b_sel & 1) * 8;

#pragma unroll 1
    for (int kc = 0; kc < H_DIM / PBK; ++kc) {
        // issue next A chunk into the other buffer
        if (kc < 3) {
            const long k0n = (long)(kc + 1) * PBK;
            const int bufn = (kc + 1) & 1;
#pragma unroll
            for (int i = 0; i < 8; ++i) {
                int e = tid + i * 256;
                int term = e >> 10;
                int r = e & 1023;
                int row = r >> 3;
                int c = r & 7;
                uint32_t dst = smb + SA0 + bufn * 2 * A_BUF +
                               (term ? A_BUF : 0) + row * LDA_B + c * 16;
                const __nv_bfloat16* src =
                    (term ? g_xlo : g_xhi) + (m0 + row) * H_DIM + k0n + c * 8;
                cp16(dst, src);
            }
            CP_COMMIT();
            CP_WAIT(1);
        } else {
            CP_WAIT(0);
        }
        __syncthreads();

        const uint32_t sa_hi = smb + SA0 + (kc & 1) * 2 * A_BUF;
        const uint32_t sa_lo = sa_hi + A_BUF;

#pragma unroll
        for (int kk = 0; kk < 4; ++kk) {
            const int kb = kk * 16;
            const int kw = kc * PBK + kb;   // k offset in resident W
            uint32_t ahi[2][4], alo[2][4], bfr[8][2];

#pragma unroll
            for (int mt = 0; mt < 2; ++mt) {
                uint32_t ra = (wm + mt * 16 + a_row) * LDA_B + (kb + a_c8) * 2;
                ldsm_x4(ahi[mt], sa_hi + ra);
                ldsm_x4(alo[mt], sa_lo + ra);
            }
#pragma unroll
            for (int ntp = 0; ntp < 4; ++ntp) {
                uint32_t rb = (wn + ntp * 16 + b_nof) * LDW_B + (kw + b_kof) * 2;
                uint32_t r[4];
                ldsm_x4(r, smb + SW_HI + rb);
                bfr[ntp * 2][0] = r[0];  bfr[ntp * 2][1] = r[1];
                bfr[ntp * 2 + 1][0] = r[2];  bfr[ntp * 2 + 1][1] = r[3];
            }
#pragma unroll
            for (int mt = 0; mt < 2; ++mt)
#pragma unroll
                for (int nt = 0; nt < 8; ++nt) {
                    mma_bf16(d[mt][nt], ahi[mt], bfr[nt]);   // A_hi * B_hi
                    mma_bf16(d[mt][nt], alo[mt], bfr[nt]);   // A_lo * B_hi
                }
#pragma unroll
            for (int ntp = 0; ntp < 4; ++ntp) {
                uint32_t rb = (wn + ntp * 16 + b_nof) * LDW_B + (kw + b_kof) * 2;
                uint32_t r[4];
                ldsm_x4(r, smb + SW_LO + rb);
                bfr[ntp * 2][0] = r[0];  bfr[ntp * 2][1] = r[1];
                bfr[ntp * 2 + 1][0] = r[2];  bfr[ntp * 2 + 1][1] = r[3];
            }
#pragma unroll
            for (int mt = 0; mt < 2; ++mt)
#pragma unroll
                for (int nt = 0; nt < 8; ++nt)
                    mma_bf16(d[mt][nt], ahi[mt], bfr[nt]);   // A_hi * B_lo
        }
        __syncthreads();   // all reads of buf done before it is re-filled
    }

    const float* sbias = (const float*)(sm + SBIAS);
    const int g  = lane >> 2;
    const int tc = lane & 3;
#pragma unroll
    for (int mt = 0; mt < 2; ++mt) {
        long r = m0 + wm + mt * 16 + g;
#pragma unroll
        for (int nt = 0; nt < 8; ++nt) {
            int cn = wn + nt * 8 + tc * 2;
            float b0 = sbias[cn], b1 = sbias[cn + 1];
            *(float2*)&g_xw[r * H_DIM + n0 + cn] =
                make_float2(d[mt][nt][0] + b0, d[mt][nt][1] + b1);
            *(float2*)&g_xw[(r + 8) * H_DIM + n0 + cn] =
                make_float2(d[mt][nt][2] + b0, d[mt][nt][3] + b1);
        }
    }
}

// ---------------------------------------------------------------------------
// Scan (unchanged, passing since R6). 128 CTAs x 512 threads, dense planes.
// ---------------------------------------------------------------------------
#define KG 16
#define K_PER 16
#define REG_K 8
#define SMEM_K 8
#define SCAN_THREADS 512

#define WSM_U64 (KG * SMEM_K * 128)
#define SCAN_SMEM_U64 (WSM_U64 + 256 + 256 + KG * 128 * 2)
#define SCAN_SMEM_BYTES (SCAN_SMEM_U64 * 8)

__global__ __launch_bounds__(SCAN_THREADS, 1) void scan_kernel(
    const float* __restrict__ xw,
    const float* __restrict__ wh,
    float* __restrict__ out)
{
    extern __shared__ __align__(1024) u64 smu[];
    u64* wsm = smu;
    u64* hd0 = smu + WSM_U64;
    u64* hd1 = hd0 + 256;
    u64* sp0 = hd1 + 256;
    u64* sp1 = sp0 + KG * 128;

    const int tid = threadIdx.x;
    const int kg  = tid >> 5;
    const int p8  = tid & 31;
    const int r0  = blockIdx.x * 2;

    const u64* whd = (const u64*)wh;

    for (int e = tid; e < WSM_U64; e += SCAN_THREADS) {
        int kgs = e >> 10;
        int kk  = (e >> 7) & 7;
        int cpx = e & 127;
        int dst = (e & ~127) + ((cpx & 3) >> 1) * 64 + (cpx >> 2) * 2 + (cpx & 1);
        wsm[dst] = whd[(kgs * K_PER + REG_K + kk) * 128 + cpx];
    }
    if (tid < 256) { hd0[tid] = 0ull; hd1[tid] = 0ull; }

    u64 wr[REG_K][4];
    const int cpb = p8 * 4;
    const int kb  = kg * K_PER;
#pragma unroll
    for (int kk = 0; kk < REG_K; ++kk)
#pragma unroll
        for (int ci = 0; ci < 4; ++ci)
            wr[kk][ci] = whd[(kb + kk) * 128 + cpb + ci];
    __syncthreads();

    const int rr = tid >> 7;
    const int cp = tid & 127;
    const u64* xwrow = (tid < 256)
        ? (const u64*)xw + ((long)(r0 + rr) * T_DIM) * 128 + cp
        : (const u64*)xw;

    const u64* wsmA = wsm + kg * (SMEM_K * 128) + p8 * 2;
    const u64* wsmB = wsmA + 64;
    const u64* hd0_t = hd0 + kb;
    const u64* hd1_t = hd1 + kb;
    ulonglong2* spA0 = (ulonglong2*)(sp0 + kg * 128 + p8 * 2);
    ulonglong2* spB0 = (ulonglong2*)(sp0 + kg * 128 + 64 + p8 * 2);
    ulonglong2* spA1 = (ulonglong2*)(sp1 + kg * 128 + p8 * 2);
    ulonglong2* spB1 = (ulonglong2*)(sp1 + kg * 128 + 64 + p8 * 2);
    const int rdoff = ((cp & 3) >> 1) * 64 + (cp >> 2) * 2 + (cp & 1);
    const u64* sprd = (rr == 0) ? sp0 : sp1;
    u64* hdw = (rr == 0) ? hd0 : hd1;

#pragma unroll 1
    for (int t = 0; t < T_DIM; ++t) {
        u64 xv = 0ull;
        if (tid < 256) xv = xwrow[(long)t * 128];

        u64 a00 = 0, a01 = 0, a02 = 0, a03 = 0;
        u64 a10 = 0, a11 = 0, a12 = 0, a13 = 0;

#pragma unroll
        for (int kk = 0; kk < REG_K; kk += 2) {
            ulonglong2 h0p = *(const ulonglong2*)&hd0_t[kk];
            ulonglong2 h1p = *(const ulonglong2*)&hd1_t[kk];
            a00 = f2fma(h0p.x, wr[kk][0], a00);
            a01 = f2fma(h0p.x, wr[kk][1], a01);
            a02 = f2fma(h0p.x, wr[kk][2], a02);
            a03 = f2fma(h0p.x, wr[kk][3], a03);
            a10 = f2fma(h1p.x, wr[kk][0], a10);
            a11 = f2fma(h1p.x, wr[kk][1], a11);
            a12 = f2fma(h1p.x, wr[kk][2], a12);
            a13 = f2fma(h1p.x, wr[kk][3], a13);
            a00 = f2fma(h0p.y, wr[kk + 1][0], a00);
            a01 = f2fma(h0p.y, wr[kk + 1][1], a01);
            a02 = f2fma(h0p.y, wr[kk + 1][2], a02);
            a03 = f2fma(h0p.y, wr[kk + 1][3], a03);
            a10 = f2fma(h1p.y, wr[kk + 1][0], a10);
            a11 = f2fma(h1p.y, wr[kk + 1][1], a11);
            a12 = f2fma(h1p.y, wr[kk + 1][2], a12);
            a13 = f2fma(h1p.y, wr[kk + 1][3], a13);
        }
#pragma unroll
        for (int kk = 0; kk < SMEM_K; kk += 2) {
            ulonglong2 h0p = *(const ulonglong2*)&hd0_t[REG_K + kk];
            ulonglong2 h1p = *(const ulonglong2*)&hd1_t[REG_K + kk];
            ulonglong2 wa0 = *(const ulonglong2*)&wsmA[kk * 128];
            ulonglong2 wb0 = *(const ulonglong2*)&wsmB[kk * 128];
            ulonglong2 wa1 = *(const ulonglong2*)&wsmA[(kk + 1) * 128];
            ulonglong2 wb1 = *(const ulonglong2*)&wsmB[(kk + 1) * 128];
            a00 = f2fma(h0p.x, wa0.x, a00);
            a01 = f2fma(h0p.x, wa0.y, a01);
            a02 = f2fma(h0p.x, wb0.x, a02);
            a03 = f2fma(h0p.x, wb0.y, a03);
            a10 = f2fma(h1p.x, wa0.x, a10);
            a11 = f2fma(h1p.x, wa0.y, a11);
            a12 = f2fma(h1p.x, wb0.x, a12);
            a13 = f2fma(h1p.x, wb0.y, a13);
            a00 = f2fma(h0p.y, wa1.x, a00);
            a01 = f2fma(h0p.y, wa1.y, a01);
            a02 = f2fma(h0p.y, wb1.x, a02);
            a03 = f2fma(h0p.y, wb1.y, a03);
            a10 = f2fma(h1p.y, wa1.x, a10);
            a11 = f2fma(h1p.y, wa1.y, a11);
            a12 = f2fma(h1p.y, wb1.x, a12);
            a13 = f2fma(h1p.y, wb1.y, a13);
        }

        spA0[0] = make_ulonglong2(a00, a01);
        spB0[0] = make_ulonglong2(a02, a03);
        spA1[0] = make_ulonglong2(a10, a11);
        spB1[0] = make_ulonglong2(a12, a13);
        __syncthreads();

        if (tid < 256) {
            u64 s = sprd[rdoff];
#pragma unroll
            for (int g = 1; g < KG; ++g)
                s = f2add(s, sprd[g * 128 + rdoff]);
            s = f2add(s, xv);
            float2 sv = upk(s);
            float v0 = tanhf(sv.x);
            float v1 = tanhf(sv.y);
            *(ulonglong2*)&hdw[2 * cp] = make_ulonglong2(dupf(v0), dupf(v1));
            if (t == T_DIM - 1)
                *(float2*)&out[(long)(r0 + rr) * H_DIM + 2 * cp] =
                    make_float2(v0, v1);
        }
        __syncthreads();
    }
}

// ---------------------------------------------------------------------------
extern "C" void kernel_launch(void* const* d_in, const int* in_sizes, int n_in,
                              void* d_out, int out_size)
{
    const float* x    = (const float*)d_in[0];
    const float* wx   = (const float*)d_in[1];
    const float* wh   = (const float*)d_in[2];
    const float* bias = (const float*)d_in[3];
    float* out = (float*)d_out;

    float* xw;
    cudaGetSymbolAddress((void**)&xw, g_xw);

    prep_w<<<H_DIM, H_DIM>>>(wx);
    prep_x<<<(M_TOTAL * H_DIM / 4) / 256, 256>>>((const float4*)x);

    cudaFuncSetAttribute(proj_kernel,
                         cudaFuncAttributeMaxDynamicSharedMemorySize, PS_TOTAL);
    dim3 pgrid(H_DIM / PN, M_TOTAL / PM);   // (2, 4096)
    proj_kernel<<<pgrid, 256, PS_TOTAL>>>(bias);

    cudaFuncSetAttribute(scan_kernel,
                         cudaFuncAttributeMaxDynamicSharedMemorySize,
                         SCAN_SMEM_BYTES);
    scan_kernel<<<B_DIM / 2, SCAN_THREADS, SCAN_SMEM_BYTES>>>(xw, wh, out);
}

// round 9
// speedup vs baseline: 1.1944x; 1.1944x over previous
#include <cuda_runtime.h>
#include <cuda_bf16.h>
#include <cstdint>

// ---------------------------------------------------------------------------
// Vanilla RNN: h_t = tanh(h_{t-1} @ wh + x_t @ wx + b), out = h_T  [B,1,H]
// B=256, T=2048, H=256 fp32.
// Phase 0: prep_w / prep_x — bf16 hi/lo splits of wx^T and x
// Phase 1: proj — xw = x @ wx + b via mma.sync bf16x3, cp.async pipelined
// Phase 2: scan v3 — KG=8 (short reduce), combined h layout, fast tanh
// ---------------------------------------------------------------------------

#define B_DIM 256
#define T_DIM 2048
#define H_DIM 256
#define M_TOTAL (B_DIM * T_DIM)

typedef unsigned long long u64;

__device__ float g_xw[(size_t)M_TOTAL * H_DIM];              // 512 MB scratch
__device__ __nv_bfloat16 g_wT_hi[H_DIM * H_DIM];             // wx^T hi, [n][k]
__device__ __nv_bfloat16 g_wT_lo[H_DIM * H_DIM];             // wx^T lo, [n][k]
__device__ __nv_bfloat16 g_xhi[(size_t)M_TOTAL * H_DIM];     // x hi (256 MB)
__device__ __nv_bfloat16 g_xlo[(size_t)M_TOTAL * H_DIM];     // x lo (256 MB)

// ------------------------- packed f32x2 helpers -----------------------------
__device__ __forceinline__ u64 f2fma(u64 a, u64 b, u64 c) {
    u64 d; asm("fma.rn.f32x2 %0,%1,%2,%3;" : "=l"(d) : "l"(a), "l"(b), "l"(c));
    return d;
}
__device__ __forceinline__ u64 f2add(u64 a, u64 b) {
    u64 d; asm("add.rn.f32x2 %0,%1,%2;" : "=l"(d) : "l"(a), "l"(b));
    return d;
}
__device__ __forceinline__ u64 dupf(float x) {
    u64 d; asm("mov.b64 %0,{%1,%1};" : "=l"(d) : "f"(x));
    return d;
}
__device__ __forceinline__ float2 upk(u64 d) {
    float2 v; asm("mov.b64 {%0,%1},%2;" : "=f"(v.x), "=f"(v.y) : "l"(d));
    return v;
}
// tanh(x) = 1 - 2/(exp(2x)+1) via MUFU ex2/rcp (abs err ~2e-7, 5 instr)
__device__ __forceinline__ float fast_tanh(float x) {
    float e, r;
    asm("ex2.approx.f32 %0, %1;" : "=f"(e) : "f"(x * 2.8853900817779268f));
    asm("rcp.approx.f32 %0, %1;" : "=f"(r) : "f"(e + 1.0f));
    return fmaf(-2.0f, r, 1.0f);
}

// ------------------------- mma.sync / cp.async helpers ----------------------
__device__ __forceinline__ uint32_t smem_u32(const void* p) {
    uint32_t a;
    asm("{ .reg .u64 t; cvta.to.shared.u64 t, %1; cvt.u32.u64 %0, t; }"
        : "=r"(a) : "l"(p));
    return a;
}
__device__ __forceinline__ void ldsm_x4(uint32_t* r, uint32_t addr) {
    asm volatile("ldmatrix.sync.aligned.m8n8.x4.shared.b16 {%0,%1,%2,%3}, [%4];"
                 : "=r"(r[0]), "=r"(r[1]), "=r"(r[2]), "=r"(r[3]) : "r"(addr));
}
__device__ __forceinline__ void mma_bf16(float* d, const uint32_t* a,
                                         const uint32_t* b) {
    asm volatile(
        "mma.sync.aligned.m16n8k16.row.col.f32.bf16.bf16.f32 "
        "{%0,%1,%2,%3},{%4,%5,%6,%7},{%8,%9},{%0,%1,%2,%3};"
        : "+f"(d[0]), "+f"(d[1]), "+f"(d[2]), "+f"(d[3])
        : "r"(a[0]), "r"(a[1]), "r"(a[2]), "r"(a[3]), "r"(b[0]), "r"(b[1]));
}
__device__ __forceinline__ void cp16(uint32_t dst, const void* src) {
    asm volatile("cp.async.cg.shared.global [%0], [%1], 16;"
                 :: "r"(dst), "l"(src));
}
#define CP_COMMIT() asm volatile("cp.async.commit_group;" ::: "memory")
#define CP_WAIT(n)  asm volatile("cp.async.wait_group %0;" :: "n"(n) : "memory")

// ---------------------------------------------------------------------------
// Prep kernels
// ---------------------------------------------------------------------------
__global__ void prep_w(const float* __restrict__ wx) {
    int k = blockIdx.x;
    int n = threadIdx.x;
    float v = wx[k * H_DIM + n];
    __nv_bfloat16 hi = __float2bfloat16(v);
    __nv_bfloat16 lo = __float2bfloat16(v - __bfloat162float(hi));
    g_wT_hi[n * H_DIM + k] = hi;
    g_wT_lo[n * H_DIM + k] = lo;
}

__global__ __launch_bounds__(256) void prep_x(const float4* __restrict__ x) {
    size_t i = (size_t)blockIdx.x * 256 + threadIdx.x;
    float4 v = x[i];
    __nv_bfloat16 h0 = __float2bfloat16(v.x);
    __nv_bfloat16 h1 = __float2bfloat16(v.y);
    __nv_bfloat16 h2 = __float2bfloat16(v.z);
    __nv_bfloat16 h3 = __float2bfloat16(v.w);
    __nv_bfloat16 l0 = __float2bfloat16(v.x - __bfloat162float(h0));
    __nv_bfloat16 l1 = __float2bfloat16(v.y - __bfloat162float(h1));
    __nv_bfloat16 l2 = __float2bfloat16(v.z - __bfloat162float(h2));
    __nv_bfloat16 l3 = __float2bfloat16(v.w - __bfloat162float(h3));
    __nv_bfloat162 hp0{h0, h1}, hp1{h2, h3}, lp0{l0, l1}, lp1{l2, l3};
    u64 hw = (u64)(*(uint32_t*)&hp0) | ((u64)(*(uint32_t*)&hp1) << 32);
    u64 lw = (u64)(*(uint32_t*)&lp0) | ((u64)(*(uint32_t*)&lp1) << 32);
    ((u64*)g_xhi)[i] = hw;
    ((u64*)g_xlo)[i] = lw;
}

// ---------------------------------------------------------------------------
// Proj (unchanged, passing since R8): mma.sync bf16x3, W resident, A pipelined
// ---------------------------------------------------------------------------
#define PM 128
#define PN 128
#define PBK 64
#define LDA_B 144
#define LDW_B 528

#define SW_HI 0
#define SW_LO (SW_HI + PN * LDW_B)
#define SA0   (SW_LO + PN * LDW_B)
#define A_BUF (PM * LDA_B)
#define SBIAS (SA0 + 4 * A_BUF)
#define PS_TOTAL (SBIAS + PN * 4)

__global__ __launch_bounds__(256) void proj_kernel(const float* __restrict__ bias)
{
    extern __shared__ __align__(128) char sm[];
    const uint32_t smb = smem_u32(sm);
    const int tid  = threadIdx.x;
    const int wid  = tid >> 5;
    const int lane = tid & 31;
    const int n0 = blockIdx.x * PN;
    const long m0 = (long)blockIdx.y * PM;
    const int wm = (wid >> 1) * 32;
    const int wn = (wid & 1) * 64;

#pragma unroll
    for (int i = 0; i < 32; ++i) {
        int e = tid + i * 256;
        int term = e >> 12;
        int r = e & 4095;
        int n = r >> 5;
        int c = r & 31;
        uint32_t dst = smb + (term ? SW_LO : SW_HI) + n * LDW_B + c * 16;
        const __nv_bfloat16* src =
            (term ? g_wT_lo : g_wT_hi) + (n0 + n) * H_DIM + c * 8;
        cp16(dst, src);
    }
    CP_COMMIT();

    {
#pragma unroll
        for (int i = 0; i < 8; ++i) {
            int e = tid + i * 256;
            int term = e >> 10;
            int r = e & 1023;
            int row = r >> 3;
            int c = r & 7;
            uint32_t dst = smb + SA0 + (term ? A_BUF : 0) + row * LDA_B + c * 16;
            const __nv_bfloat16* src =
                (term ? g_xlo : g_xhi) + (m0 + row) * H_DIM + c * 8;
            cp16(dst, src);
        }
    }
    CP_COMMIT();

    if (tid < PN) ((float*)(sm + SBIAS))[tid] = bias[n0 + tid];

    float d[2][8][4];
#pragma unroll
    for (int mt = 0; mt < 2; ++mt)
#pragma unroll
        for (int nt = 0; nt < 8; ++nt)
#pragma unroll
            for (int i = 0; i < 4; ++i) d[mt][nt][i] = 0.0f;

    const int a_row = lane & 15;
    const int a_c8  = (lane >> 4) * 8;
    const int b_sel = lane >> 3;
    const int b_nof = (b_sel >> 1) * 8 + (lane & 7);
    const int b_kof = (b_sel & 1) * 8;

#pragma unroll 1
    for (int kc = 0; kc < H_DIM / PBK; ++kc) {
        if (kc < 3) {
            const long k0n = (long)(kc + 1) * PBK;
            const int bufn = (kc + 1) & 1;
#pragma unroll
            for (int i = 0; i < 8; ++i) {
                int e = tid + i * 256;
                int term = e >> 10;
                int r = e & 1023;
                int row = r >> 3;
                int c = r & 7;
                uint32_t dst = smb + SA0 + bufn * 2 * A_BUF +
                               (term ? A_BUF : 0) + row * LDA_B + c * 16;
                const __nv_bfloat16* src =
                    (term ? g_xlo : g_xhi) + (m0 + row) * H_DIM + k0n + c * 8;
                cp16(dst, src);
            }
            CP_COMMIT();
            CP_WAIT(1);
        } else {
            CP_WAIT(0);
        }
        __syncthreads();

        const uint32_t sa_hi = smb + SA0 + (kc & 1) * 2 * A_BUF;
        const uint32_t sa_lo = sa_hi + A_BUF;

#pragma unroll
        for (int kk = 0; kk < 4; ++kk) {
            const int kb = kk * 16;
            const int kw = kc * PBK + kb;
            uint32_t ahi[2][4], alo[2][4], bfr[8][2];

#pragma unroll
            for (int mt = 0; mt < 2; ++mt) {
                uint32_t ra = (wm + mt * 16 + a_row) * LDA_B + (kb + a_c8) * 2;
                ldsm_x4(ahi[mt], sa_hi + ra);
                ldsm_x4(alo[mt], sa_lo + ra);
            }
#pragma unroll
            for (int ntp = 0; ntp < 4; ++ntp) {
                uint32_t rb = (wn + ntp * 16 + b_nof) * LDW_B + (kw + b_kof) * 2;
                uint32_t r[4];
                ldsm_x4(r, smb + SW_HI + rb);
                bfr[ntp * 2][0] = r[0];  bfr[ntp * 2][1] = r[1];
                bfr[ntp * 2 + 1][0] = r[2];  bfr[ntp * 2 + 1][1] = r[3];
            }
#pragma unroll
            for (int mt = 0; mt < 2; ++mt)
#pragma unroll
                for (int nt = 0; nt < 8; ++nt) {
                    mma_bf16(d[mt][nt], ahi[mt], bfr[nt]);
                    mma_bf16(d[mt][nt], alo[mt], bfr[nt]);
                }
#pragma unroll
            for (int ntp = 0; ntp < 4; ++ntp) {
                uint32_t rb = (wn + ntp * 16 + b_nof) * LDW_B + (kw + b_kof) * 2;
                uint32_t r[4];
                ldsm_x4(r, smb + SW_LO + rb);
                bfr[ntp * 2][0] = r[0];  bfr[ntp * 2][1] = r[1];
                bfr[ntp * 2 + 1][0] = r[2];  bfr[ntp * 2 + 1][1] = r[3];
            }
#pragma unroll
            for (int mt = 0; mt < 2; ++mt)
#pragma unroll
                for (int nt = 0; nt < 8; ++nt)
                    mma_bf16(d[mt][nt], ahi[mt], bfr[nt]);
        }
        __syncthreads();
    }

    const float* sbias = (const float*)(sm + SBIAS);
    const int g  = lane >> 2;
    const int tc = lane & 3;
#pragma unroll
    for (int mt = 0; mt < 2; ++mt) {
        long r = m0 + wm + mt * 16 + g;
#pragma unroll
        for (int nt = 0; nt < 8; ++nt) {
            int cn = wn + nt * 8 + tc * 2;
            float b0 = sbias[cn], b1 = sbias[cn + 1];
            *(float2*)&g_xw[r * H_DIM + n0 + cn] =
                make_float2(d[mt][nt][0] + b0, d[mt][nt][1] + b1);
            *(float2*)&g_xw[(r + 8) * H_DIM + n0 + cn] =
                make_float2(d[mt][nt][2] + b0, d[mt][nt][3] + b1);
        }
    }
}

// ---------------------------------------------------------------------------
// Scan v3. 128 CTAs x 512 threads, 2 batch rows per CTA.
// 8 k-groups x 64 threads; thread (kg, p) covers k-range 32 (16 reg-cached,
// 16 from smem) and colpairs {2p, 2p+1}. h stored ONCE as (h0[k],h1[k]) u64,
// dup'd in-register (ALU, hidden under FMA). Short 8-deep reduction, MUFU tanh.
// All smem accesses dense/broadcast by construction.
// ---------------------------------------------------------------------------
#define KGn 8
#define KRANGE 32
#define RK 16
#define SK 16
#define SCAN_THREADS 512

#define WSM_U64 (KGn * SK * 128)                 // 16384 (128 KB)
#define HS_OFF  WSM_U64                          // hs: 256 u64 (2 KB)
#define SP_OFF  (WSM_U64 + 256)                  // sp: 8*2*128 u64 (16 KB)
#define SCAN_SMEM_BYTES ((WSM_U64 + 256 + KGn * 2 * 128) * 8)

__global__ __launch_bounds__(SCAN_THREADS, 1) void scan_kernel(
    const float* __restrict__ xw,
    const float* __restrict__ wh,
    float* __restrict__ out)
{
    extern __shared__ __align__(1024) u64 smu[];
    u64* wsm = smu;
    u64* hs  = smu + HS_OFF;
    u64* sp  = smu + SP_OFF;

    const int tid = threadIdx.x;
    const int kg  = tid >> 6;          // 0..7
    const int p   = tid & 63;          // 0..63
    const int r0  = blockIdx.x * 2;

    const u64* whd = (const u64*)wh;   // wh as colpairs [256][128]

    // stage smem W half: group kg's k in [kg*32+16, kg*32+32), natural cp order
    for (int e = tid; e < WSM_U64; e += SCAN_THREADS) {
        int kgi = e >> 11;             // e / (16*128)
        int kk  = (e >> 7) & 15;
        int cpx = e & 127;
        wsm[e] = whd[(kgi * KRANGE + RK + kk) * 128 + cpx];
    }
    if (tid < 256) hs[tid] = 0ull;

    // reg-cache W: group kg's k in [kg*32, kg*32+16), colpairs 2p, 2p+1
    u64 wr[RK][2];
#pragma unroll
    for (int kk = 0; kk < RK; ++kk) {
        wr[kk][0] = whd[(kg * KRANGE + kk) * 128 + 2 * p];
        wr[kk][1] = whd[(kg * KRANGE + kk) * 128 + 2 * p + 1];
    }
    __syncthreads();

    const int rr = tid >> 7;           // reduce role (tid < 256): row
    const int cp = tid & 127;          // reduce colpair
    const u64* xwrow = (tid < 256)
        ? (const u64*)xw + ((long)(r0 + rr) * T_DIM) * 128 + cp
        : (const u64*)xw;

    const u64* hp = hs + kg * KRANGE;
    const u64* wp = wsm + kg * (SK * 128) + 2 * p;
    ulonglong2* sp0w = (ulonglong2*)(sp + (kg * 2 + 0) * 128 + 2 * p);
    ulonglong2* sp1w = (ulonglong2*)(sp + (kg * 2 + 1) * 128 + 2 * p);
    float* hsf = (float*)hs;

#pragma unroll 1
    for (int t = 0; t < T_DIM; ++t) {
        u64 xv = 0ull;
        if (tid < 256) xv = xwrow[(long)t * 128];

        u64 a00 = 0, a01 = 0, a10 = 0, a11 = 0;

        // ---- reg half ----
#pragma unroll
        for (int kk = 0; kk < RK; kk += 2) {
            ulonglong2 hh = *(const ulonglong2*)&hp[kk];
            float2 ha = upk(hh.x), hb = upk(hh.y);
            u64 h0a = dupf(ha.x), h1a = dupf(ha.y);
            u64 h0b = dupf(hb.x), h1b = dupf(hb.y);
            a00 = f2fma(h0a, wr[kk][0], a00);
            a01 = f2fma(h0a, wr[kk][1], a01);
            a10 = f2fma(h1a, wr[kk][0], a10);
            a11 = f2fma(h1a, wr[kk][1], a11);
            a00 = f2fma(h0b, wr[kk + 1][0], a00);
            a01 = f2fma(h0b, wr[kk + 1][1], a01);
            a10 = f2fma(h1b, wr[kk + 1][0], a10);
            a11 = f2fma(h1b, wr[kk + 1][1], a11);
        }
        // ---- smem half ----
#pragma unroll
        for (int kk = 0; kk < SK; kk += 2) {
            ulonglong2 hh = *(const ulonglong2*)&hp[RK + kk];
            ulonglong2 w0 = *(const ulonglong2*)&wp[kk * 128];
            ulonglong2 w1 = *(const ulonglong2*)&wp[(kk + 1) * 128];
            float2 ha = upk(hh.x), hb = upk(hh.y);
            u64 h0a = dupf(ha.x), h1a = dupf(ha.y);
            u64 h0b = dupf(hb.x), h1b = dupf(hb.y);
            a00 = f2fma(h0a, w0.x, a00);
            a01 = f2fma(h0a, w0.y, a01);
            a10 = f2fma(h1a, w0.x, a10);
            a11 = f2fma(h1a, w0.y, a11);
            a00 = f2fma(h0b, w1.x, a00);
            a01 = f2fma(h0b, w1.y, a01);
            a10 = f2fma(h1b, w1.x, a10);
            a11 = f2fma(h1b, w1.y, a11);
        }

        sp0w[0] = make_ulonglong2(a00, a01);
        sp1w[0] = make_ulonglong2(a10, a11);
        __syncthreads();

        if (tid < 256) {
            u64 s = sp[rr * 128 + cp];
#pragma unroll
            for (int g = 1; g < KGn; ++g)
                s = f2add(s, sp[(g * 2 + rr) * 128 + cp]);
            s = f2add(s, xv);
            float2 sv = upk(s);
            float v0 = fast_tanh(sv.x);
            float v1 = fast_tanh(sv.y);
            // hs[k] = (h0[k], h1[k]); this thread owns cols 2cp, 2cp+1, row rr
            hsf[(2 * cp) * 2 + rr]     = v0;
            hsf[(2 * cp + 1) * 2 + rr] = v1;
            if (t == T_DIM - 1)
                *(float2*)&out[(long)(r0 + rr) * H_DIM + 2 * cp] =
                    make_float2(v0, v1);
        }
        __syncthreads();
    }
}

// ---------------------------------------------------------------------------
extern "C" void kernel_launch(void* const* d_in, const int* in_sizes, int n_in,
                              void* d_out, int out_size)
{
    const float* x    = (const float*)d_in[0];
    const float* wx   = (const float*)d_in[1];
    const float* wh   = (const float*)d_in[2];
    const float* bias = (const float*)d_in[3];
    float* out = (float*)d_out;

    float* xw;
    cudaGetSymbolAddress((void**)&xw, g_xw);

    prep_w<<<H_DIM, H_DIM>>>(wx);
    prep_x<<<(M_TOTAL * H_DIM / 4) / 256, 256>>>((const float4*)x);

    cudaFuncSetAttribute(proj_kernel,
                         cudaFuncAttributeMaxDynamicSharedMemorySize, PS_TOTAL);
    dim3 pgrid(H_DIM / PN, M_TOTAL / PM);   // (2, 4096)
    proj_kernel<<<pgrid, 256, PS_TOTAL>>>(bias);

    cudaFuncSetAttribute(scan_kernel,
                         cudaFuncAttributeMaxDynamicSharedMemorySize,
                         SCAN_SMEM_BYTES);
    scan_kernel<<<B_DIM / 2, SCAN_THREADS, SCAN_SMEM_BYTES>>>(xw, wh, out);
}